// round 6
// baseline (speedup 1.0000x reference)
#include <cuda_runtime.h>
#include <mma.h>
using namespace nvcuda;

#define NN 50000
#define F  64        // in feats
#define KK 256       // F * K(=4) = GEMM K dim
#define OF 256       // out feats
#define EE 800000

// ---- scratch (static __device__ arrays; no allocation allowed) ----
__device__ float g_dsq[NN];                 // deg accumulator -> rsqrt(max(deg,1))
__device__ int   g_rowptr[NN + 1];          // CSR row pointers (in-edges by dst)
__device__ int   g_fill[NN];                // fill counters
__device__ int   g_col[EE];                 // CSR column (src node of each in-edge)
__device__ float g_Xt[(size_t)NN * KK];     // packed [X0 | X1 | X2 | X3]

// ---------------- degree ----------------
__global__ void zero_dsq_kernel() {
    int i = blockIdx.x * blockDim.x + threadIdx.x;
    if (i < NN) g_dsq[i] = 0.0f;
}

__global__ void deg_kernel(const int* __restrict__ dst, int E) {
    int e = blockIdx.x * blockDim.x + threadIdx.x;
    if (e < E) atomicAdd(&g_dsq[dst[e]], 1.0f);
}

// scan raw float degrees -> exclusive rowptr; zero fill; write dsq = rsqrt(max(deg,1))
__global__ __launch_bounds__(1024)
void scan_kernel() {
    __shared__ int part[1024];
    int t = threadIdx.x;
    const int CH = (NN + 1023) / 1024;   // 49
    int base = t * CH;
    int s = 0;
#pragma unroll 4
    for (int i = 0; i < CH; i++) {
        int idx = base + i;
        if (idx < NN) s += (int)g_dsq[idx];
    }
    part[t] = s;
    __syncthreads();
    for (int off = 1; off < 1024; off <<= 1) {
        int v = 0;
        if (t >= off) v = part[t - off];
        __syncthreads();
        if (t >= off) part[t] += v;
        __syncthreads();
    }
    int run = part[t] - s;   // exclusive prefix at chunk start
    for (int i = 0; i < CH; i++) {
        int idx = base + i;
        if (idx < NN) {
            float deg = g_dsq[idx];
            g_rowptr[idx] = run;
            run += (int)deg;
            g_fill[idx] = 0;
            g_dsq[idx] = rsqrtf(fmaxf(deg, 1.0f));
        }
    }
    if (t == 1023) g_rowptr[NN] = run;
}

__global__ void fill_kernel(const int* __restrict__ src,
                            const int* __restrict__ dst, int E) {
    int e = blockIdx.x * blockDim.x + threadIdx.x;
    if (e >= E) return;
    int d = dst[e];
    int pos = g_rowptr[d] + atomicAdd(&g_fill[d], 1);
    g_col[pos] = src[e];
}

// ---------------- init: X0 into Xt chunk0 ----------------
__global__ void init_kernel(const float* __restrict__ sig) {
    int i = blockIdx.x * blockDim.x + threadIdx.x;
    if (i >= NN * (F / 4)) return;          // float4 granularity
    int row = i >> 4;
    int c4  = i & 15;
    float4 v = ((const float4*)sig)[i];
    ((float4*)(g_Xt + (size_t)row * KK))[c4] = v;
}

// ---------------- fused Chebyshev step: gather + combine, no atomics ----------------
// 16 threads per node; each lane owns one float4 (4 feats) of the 64-feat row.
//   agg = sum_{in-edges} dsq[src] * Xt[src, in_chunk]
//   L = dsq[v] * agg
//   step 1: out = -r*L + (r-1)*X_p1
//   step 2: out = -2r*L + 2(r-1)*X_p1 - X_p2
__global__ __launch_bounds__(256)
void cheb_step_kernel(const float* __restrict__ lam,
                      int in_off, int out_off, int p1_off, int p2_off, int step) {
    int gtid = blockIdx.x * blockDim.x + threadIdx.x;
    int v = gtid >> 4;
    int lane = gtid & 15;
    if (v >= NN) return;

    int p   = g_rowptr[v];
    int end = g_rowptr[v + 1];
    float ax = 0.f, ay = 0.f, az = 0.f, aw = 0.f;

    const float4* Xin = (const float4*)(g_Xt + in_off);   // stride KK/4 float4 per row
    for (; p + 1 < end; p += 2) {
        int s0 = g_col[p];
        int s1 = g_col[p + 1];
        float d0 = g_dsq[s0];
        float d1 = g_dsq[s1];
        float4 x0 = Xin[(size_t)s0 * (KK / 4) + lane];
        float4 x1 = Xin[(size_t)s1 * (KK / 4) + lane];
        ax += d0 * x0.x + d1 * x1.x;
        ay += d0 * x0.y + d1 * x1.y;
        az += d0 * x0.z + d1 * x1.z;
        aw += d0 * x0.w + d1 * x1.w;
    }
    if (p < end) {
        int s0 = g_col[p];
        float d0 = g_dsq[s0];
        float4 x0 = Xin[(size_t)s0 * (KK / 4) + lane];
        ax += d0 * x0.x;
        ay += d0 * x0.y;
        az += d0 * x0.z;
        aw += d0 * x0.w;
    }

    float dsv = g_dsq[v];
    float r = 2.0f / lam[0];
    float Lx = ax * dsv, Ly = ay * dsv, Lz = az * dsv, Lw = aw * dsv;

    const float* base = g_Xt + (size_t)v * KK + lane * 4;
    float4 p1 = *(const float4*)(base + p1_off);
    float4 out;
    if (step == 1) {
        float c = r - 1.0f;
        out.x = -r * Lx + c * p1.x;
        out.y = -r * Ly + c * p1.y;
        out.z = -r * Lz + c * p1.z;
        out.w = -r * Lw + c * p1.w;
    } else {
        float4 p2 = *(const float4*)(base + p2_off);
        float c = 2.0f * (r - 1.0f);
        out.x = -2.0f * r * Lx + c * p1.x - p2.x;
        out.y = -2.0f * r * Ly + c * p1.y - p2.y;
        out.z = -2.0f * r * Lz + c * p1.z - p2.z;
        out.w = -2.0f * r * Lw + c * p1.w - p2.w;
    }
    *(float4*)(g_Xt + (size_t)v * KK + out_off + lane * 4) = out;
}

// ---------------- 3-stage pipelined tf32 tensor-core GEMM + bias + ReLU ----------------
// C[M, OF] = relu(Xt[M, KK] @ W[KK, OF] + b)
#define GBM 128
#define GBN 128
#define GBK 16
#define AROW 28                    // padded floats per A row (16 + 12)
#define BROW 140                   // padded floats per B row (128 + 12)
#define ASTG (GBM * AROW)          // 3584
#define STG  (ASTG + GBK * BROW)   // 3584 + 2240 = 5824 floats / stage
#define NSTG 3

__device__ __forceinline__ void cp16(float* dstp, const float* src, int sz) {
    unsigned saddr = (unsigned)__cvta_generic_to_shared(dstp);
    asm volatile("cp.async.ca.shared.global [%0], [%1], 16, %2;"
                 :: "r"(saddr), "l"(src), "r"(sz));
}

__global__ __launch_bounds__(256)
void gemm_tf32(const float* __restrict__ W, const float* __restrict__ bias,
               float* __restrict__ C, int M) {
    __shared__ float sm[NSTG * STG];   // ~70 KB

    int bx = blockIdx.x, by = blockIdx.y;
    int tid = threadIdx.x;
    int warp = tid >> 5, lane = tid & 31;
    int wm = warp >> 2;   // 0..1 : 64-row slab
    int wn = warp & 3;    // 0..3 : 32-col slab

    wmma::fragment<wmma::accumulator, 16, 16, 8, float> acc[4][2];
#pragma unroll
    for (int i = 0; i < 4; i++)
#pragma unroll
        for (int j = 0; j < 2; j++) wmma::fill_fragment(acc[i][j], 0.0f);

    const int NT = KK / GBK;   // 16 stages

    auto load_stage = [&](int t, int stg) {
        float* s = sm + stg * STG;
        int k0 = t * GBK;
#pragma unroll
        for (int it = 0; it < 2; it++) {            // A: 512 float4
            int idx = tid + it * 256;
            int row = idx >> 2, c4 = idx & 3;
            int gr = by * GBM + row;
            int grc = (gr < M) ? gr : (M - 1);
            const float* srcp = g_Xt + (size_t)grc * KK + k0 + c4 * 4;
            cp16(s + row * AROW + c4 * 4, srcp, (gr < M) ? 16 : 0);
        }
#pragma unroll
        for (int it = 0; it < 2; it++) {            // B: 512 float4
            int idx = tid + it * 256;
            int row = idx >> 5, c4 = idx & 31;
            const float* srcp = W + (size_t)(k0 + row) * OF + bx * GBN + c4 * 4;
            cp16(s + ASTG + row * BROW + c4 * 4, srcp, 16);
        }
        asm volatile("cp.async.commit_group;");
    };

    load_stage(0, 0);
    load_stage(1, 1);

    for (int t = 0; t < NT; t++) {
        if (t + 2 < NT) {
            load_stage(t + 2, (t + 2) % NSTG);
            asm volatile("cp.async.wait_group 2;");
        } else if (t + 1 < NT) {
            asm volatile("cp.async.wait_group 1;");
        } else {
            asm volatile("cp.async.wait_group 0;");
        }
        __syncthreads();

        const float* s = sm + (t % NSTG) * STG;
#pragma unroll
        for (int kk = 0; kk < GBK; kk += 8) {
            wmma::fragment<wmma::matrix_a, 16, 16, 8, wmma::precision::tf32, wmma::row_major> af[4];
            wmma::fragment<wmma::matrix_b, 16, 16, 8, wmma::precision::tf32, wmma::row_major> bf[2];
#pragma unroll
            for (int i = 0; i < 4; i++) {
                wmma::load_matrix_sync(af[i], s + (wm * 64 + i * 16) * AROW + kk, AROW);
#pragma unroll
                for (int e = 0; e < af[i].num_elements; e++)
                    af[i].x[e] = wmma::__float_to_tf32(af[i].x[e]);
            }
#pragma unroll
            for (int j = 0; j < 2; j++) {
                wmma::load_matrix_sync(bf[j], s + ASTG + kk * BROW + wn * 32 + j * 16, BROW);
#pragma unroll
                for (int e = 0; e < bf[j].num_elements; e++)
                    bf[j].x[e] = wmma::__float_to_tf32(bf[j].x[e]);
            }
#pragma unroll
            for (int i = 0; i < 4; i++)
#pragma unroll
                for (int j = 0; j < 2; j++)
                    wmma::mma_sync(acc[i][j], af[i], bf[j], acc[i][j]);
        }
        __syncthreads();
    }

    // epilogue: stage fragments through (reused) smem, add bias + relu
    float* Cw = sm + warp * 256;
#pragma unroll
    for (int i = 0; i < 4; i++) {
#pragma unroll
        for (int j = 0; j < 2; j++) {
            wmma::store_matrix_sync(Cw, acc[i][j], 16, wmma::mem_row_major);
            __syncwarp();
            int r0 = by * GBM + wm * 64 + i * 16;
            int c0 = bx * GBN + wn * 32 + j * 16;
            int lr = lane >> 1;
            int lc = (lane & 1) * 8;
            int row = r0 + lr;
            if (row < M) {
#pragma unroll
                for (int c = 0; c < 8; c += 4) {
                    int col = c0 + lc + c;
                    float4 o;
                    o.x = fmaxf(Cw[lr * 16 + lc + c + 0] + bias[col + 0], 0.0f);
                    o.y = fmaxf(Cw[lr * 16 + lc + c + 1] + bias[col + 1], 0.0f);
                    o.z = fmaxf(Cw[lr * 16 + lc + c + 2] + bias[col + 2], 0.0f);
                    o.w = fmaxf(Cw[lr * 16 + lc + c + 3] + bias[col + 3], 0.0f);
                    *(float4*)(C + (size_t)row * OF + col) = o;
                }
            }
            __syncwarp();
        }
    }
}

// ---------------- launch ----------------
extern "C" void kernel_launch(void* const* d_in, const int* in_sizes, int n_in,
                              void* d_out, int out_size) {
    const float* signal = (const float*)d_in[0];
    const int*   src    = (const int*)d_in[1];
    const int*   dst    = (const int*)d_in[2];
    const float* lam    = (const float*)d_in[3];
    const float* W      = (const float*)d_in[4];
    const float* b      = (const float*)d_in[5];
    float* out = (float*)d_out;

    const int E = in_sizes[1];
    const int EB = (E + 255) / 256;

    // degrees + CSR (dsqrt fused into scan)
    zero_dsq_kernel<<<(NN + 255) / 256, 256>>>();
    deg_kernel<<<EB, 256>>>(dst, E);
    scan_kernel<<<1, 1024>>>();
    fill_kernel<<<EB, 256>>>(src, dst, E);

    // X0
    init_kernel<<<(NN * 16 + 255) / 256, 256>>>(signal);

    // Chebyshev passes (16 threads per node, fused gather+combine)
    const int CB = (NN * 16 + 255) / 256;   // 3125 blocks
    cheb_step_kernel<<<CB, 256>>>(lam, /*in*/0,   /*out*/64,  /*p1*/0,   /*p2*/0,  1);
    cheb_step_kernel<<<CB, 256>>>(lam, /*in*/64,  /*out*/128, /*p1*/64,  /*p2*/0,  2);
    cheb_step_kernel<<<CB, 256>>>(lam, /*in*/128, /*out*/192, /*p1*/128, /*p2*/64, 2);

    // out = relu(Xt @ W + b)  -- 3-stage pipelined tf32 tensor cores
    dim3 grid(OF / GBN, (NN + GBM - 1) / GBM);
    gemm_tf32<<<grid, 256>>>(W, b, out, NN);
}

// round 7
// speedup vs baseline: 1.4230x; 1.4230x over previous
#include <cuda_runtime.h>
#include <mma.h>
using namespace nvcuda;

#define NN 50000
#define F  64        // in feats
#define KK 256       // F * K(=4) = GEMM K dim
#define OF 256       // out feats
#define EE 800000
#define SCAN_B 49    // ceil(NN/1024)

// ---- scratch (static __device__ arrays; no allocation allowed) ----
__device__ int   g_deg[NN];                 // in-degree (int)
__device__ int   g_part[SCAN_B];            // per-block partial sums
__device__ float g_dsq[NN];                 // rsqrt(max(deg,1))
__device__ int   g_rowptr[NN + 1];          // CSR row pointers (in-edges by dst)
__device__ int   g_fill[NN];                // fill counters
__device__ int   g_col[EE];                 // CSR column (src node of each in-edge)
__device__ float g_Xt[(size_t)NN * KK];     // packed [X0 | X1 | X2 | X3]

// ---------------- degree ----------------
__global__ void zero_deg_kernel() {
    int i = blockIdx.x * blockDim.x + threadIdx.x;
    if (i < NN) g_deg[i] = 0;
}

__global__ void deg_kernel(const int* __restrict__ dst, int E) {
    int e = blockIdx.x * blockDim.x + threadIdx.x;
    if (e < E) atomicAdd(&g_deg[dst[e]], 1);
}

// ---- 3-phase scan: block sums -> scan partials -> block scan + outputs ----
__global__ __launch_bounds__(1024)
void scan1_kernel() {
    __shared__ int red[32];
    int i = blockIdx.x * 1024 + threadIdx.x;
    int d = (i < NN) ? g_deg[i] : 0;
    // warp reduce
    for (int o = 16; o > 0; o >>= 1) d += __shfl_down_sync(0xffffffff, d, o);
    if ((threadIdx.x & 31) == 0) red[threadIdx.x >> 5] = d;
    __syncthreads();
    if (threadIdx.x < 32) {
        int v = red[threadIdx.x];
        for (int o = 16; o > 0; o >>= 1) v += __shfl_down_sync(0xffffffff, v, o);
        if (threadIdx.x == 0) g_part[blockIdx.x] = v;
    }
}

__global__ void scan2_kernel() {   // 1 block, 64 threads: exclusive scan of 49 partials
    __shared__ int sh[64];
    int t = threadIdx.x;
    int v = (t < SCAN_B) ? g_part[t] : 0;
    sh[t] = v;
    __syncthreads();
    for (int off = 1; off < 64; off <<= 1) {
        int u = (t >= off) ? sh[t - off] : 0;
        __syncthreads();
        sh[t] += u;
        __syncthreads();
    }
    if (t < SCAN_B) g_part[t] = sh[t] - v;   // exclusive
    if (t == 0) g_rowptr[NN] = sh[63];       // total edges (tail entries are 0)
}

__global__ __launch_bounds__(1024)
void scan3_kernel() {
    __shared__ int sh[1024];
    int t = threadIdx.x;
    int i = blockIdx.x * 1024 + t;
    int d = (i < NN) ? g_deg[i] : 0;
    sh[t] = d;
    __syncthreads();
    for (int off = 1; off < 1024; off <<= 1) {
        int u = (t >= off) ? sh[t - off] : 0;
        __syncthreads();
        sh[t] += u;
        __syncthreads();
    }
    if (i < NN) {
        g_rowptr[i] = g_part[blockIdx.x] + sh[t] - d;   // exclusive prefix
        g_fill[i] = 0;
        g_dsq[i] = rsqrtf(fmaxf((float)d, 1.0f));
    }
}

__global__ void fill_kernel(const int* __restrict__ src,
                            const int* __restrict__ dst, int E) {
    int e = blockIdx.x * blockDim.x + threadIdx.x;
    if (e >= E) return;
    int d = dst[e];
    int pos = g_rowptr[d] + atomicAdd(&g_fill[d], 1);
    g_col[pos] = src[e];
}

// ---------------- init: X0 into Xt chunk0 ----------------
__global__ void init_kernel(const float* __restrict__ sig) {
    int i = blockIdx.x * blockDim.x + threadIdx.x;
    if (i >= NN * (F / 4)) return;          // float4 granularity
    int row = i >> 4;
    int c4  = i & 15;
    float4 v = ((const float4*)sig)[i];
    ((float4*)(g_Xt + (size_t)row * KK))[c4] = v;
}

// ---------------- fused Chebyshev step: gather + combine, no atomics ----------------
// warp per node (R5-proven form)
__global__ __launch_bounds__(256)
void cheb_step_kernel(const float* __restrict__ lam,
                      int in_off, int out_off, int p1_off, int p2_off, int step) {
    int gtid = blockIdx.x * blockDim.x + threadIdx.x;
    int v = gtid >> 5;
    int lane = gtid & 31;
    if (v >= NN) return;

    int p   = g_rowptr[v];
    int end = g_rowptr[v + 1];
    float ax = 0.0f, ay = 0.0f;

    for (; p + 1 < end; p += 2) {
        int s0 = g_col[p];
        int s1 = g_col[p + 1];
        float d0 = g_dsq[s0];
        float d1 = g_dsq[s1];
        float2 x0 = *(const float2*)(g_Xt + (size_t)s0 * KK + in_off + lane * 2);
        float2 x1 = *(const float2*)(g_Xt + (size_t)s1 * KK + in_off + lane * 2);
        ax += d0 * x0.x + d1 * x1.x;
        ay += d0 * x0.y + d1 * x1.y;
    }
    if (p < end) {
        int s0 = g_col[p];
        float d0 = g_dsq[s0];
        float2 x0 = *(const float2*)(g_Xt + (size_t)s0 * KK + in_off + lane * 2);
        ax += d0 * x0.x;
        ay += d0 * x0.y;
    }

    float dsv = g_dsq[v];
    float r = 2.0f / lam[0];
    float Lx = ax * dsv, Ly = ay * dsv;

    const float* base = g_Xt + (size_t)v * KK + lane * 2;
    float2 p1 = *(const float2*)(base + p1_off);
    float2 out;
    if (step == 1) {
        out.x = -r * Lx + (r - 1.0f) * p1.x;
        out.y = -r * Ly + (r - 1.0f) * p1.y;
    } else {
        float2 p2 = *(const float2*)(base + p2_off);
        out.x = -2.0f * r * Lx + 2.0f * (r - 1.0f) * p1.x - p2.x;
        out.y = -2.0f * r * Ly + 2.0f * (r - 1.0f) * p1.y - p2.y;
    }
    *(float2*)(g_Xt + (size_t)v * KK + out_off + lane * 2) = out;
}

// ---------------- 2-stage pipelined tf32 tensor-core GEMM + bias + ReLU ----------------
// (R5-proven form, unchanged)
#define GBM 128
#define GBN 128
#define GBK 16
#define AROW 28
#define BROW 140
#define ASTG (GBM * AROW)          // 3584
#define STG  (ASTG + GBK * BROW)   // 5824 floats / stage

__device__ __forceinline__ void cp16(float* dstp, const float* src, int sz) {
    unsigned saddr = (unsigned)__cvta_generic_to_shared(dstp);
    asm volatile("cp.async.ca.shared.global [%0], [%1], 16, %2;"
                 :: "r"(saddr), "l"(src), "r"(sz));
}

__global__ __launch_bounds__(256)
void gemm_tf32(const float* __restrict__ W, const float* __restrict__ bias,
               float* __restrict__ C, int M) {
    __shared__ float sm[2 * STG];   // 46.6 KB

    int bx = blockIdx.x, by = blockIdx.y;
    int tid = threadIdx.x;
    int warp = tid >> 5, lane = tid & 31;
    int wm = warp >> 2;
    int wn = warp & 3;

    wmma::fragment<wmma::accumulator, 16, 16, 8, float> acc[4][2];
#pragma unroll
    for (int i = 0; i < 4; i++)
#pragma unroll
        for (int j = 0; j < 2; j++) wmma::fill_fragment(acc[i][j], 0.0f);

    const int NT = KK / GBK;   // 16

    auto load_stage = [&](int t, int stg) {
        float* s = sm + stg * STG;
        int k0 = t * GBK;
#pragma unroll
        for (int it = 0; it < 2; it++) {
            int idx = tid + it * 256;
            int row = idx >> 2, c4 = idx & 3;
            int gr = by * GBM + row;
            int grc = (gr < M) ? gr : (M - 1);
            const float* srcp = g_Xt + (size_t)grc * KK + k0 + c4 * 4;
            cp16(s + row * AROW + c4 * 4, srcp, (gr < M) ? 16 : 0);
        }
#pragma unroll
        for (int it = 0; it < 2; it++) {
            int idx = tid + it * 256;
            int row = idx >> 5, c4 = idx & 31;
            const float* srcp = W + (size_t)(k0 + row) * OF + bx * GBN + c4 * 4;
            cp16(s + ASTG + row * BROW + c4 * 4, srcp, 16);
        }
        asm volatile("cp.async.commit_group;");
    };

    load_stage(0, 0);

    for (int t = 0; t < NT; t++) {
        if (t + 1 < NT) {
            load_stage(t + 1, (t + 1) & 1);
            asm volatile("cp.async.wait_group 1;");
        } else {
            asm volatile("cp.async.wait_group 0;");
        }
        __syncthreads();

        const float* s = sm + (t & 1) * STG;
#pragma unroll
        for (int kk = 0; kk < GBK; kk += 8) {
            wmma::fragment<wmma::matrix_a, 16, 16, 8, wmma::precision::tf32, wmma::row_major> af[4];
            wmma::fragment<wmma::matrix_b, 16, 16, 8, wmma::precision::tf32, wmma::row_major> bf[2];
#pragma unroll
            for (int i = 0; i < 4; i++) {
                wmma::load_matrix_sync(af[i], s + (wm * 64 + i * 16) * AROW + kk, AROW);
#pragma unroll
                for (int e = 0; e < af[i].num_elements; e++)
                    af[i].x[e] = wmma::__float_to_tf32(af[i].x[e]);
            }
#pragma unroll
            for (int j = 0; j < 2; j++) {
                wmma::load_matrix_sync(bf[j], s + ASTG + kk * BROW + wn * 32 + j * 16, BROW);
#pragma unroll
                for (int e = 0; e < bf[j].num_elements; e++)
                    bf[j].x[e] = wmma::__float_to_tf32(bf[j].x[e]);
            }
#pragma unroll
            for (int i = 0; i < 4; i++)
#pragma unroll
                for (int j = 0; j < 2; j++)
                    wmma::mma_sync(acc[i][j], af[i], bf[j], acc[i][j]);
        }
        __syncthreads();
    }

    float* Cw = sm + warp * 256;
#pragma unroll
    for (int i = 0; i < 4; i++) {
#pragma unroll
        for (int j = 0; j < 2; j++) {
            wmma::store_matrix_sync(Cw, acc[i][j], 16, wmma::mem_row_major);
            __syncwarp();
            int r0 = by * GBM + wm * 64 + i * 16;
            int c0 = bx * GBN + wn * 32 + j * 16;
            int lr = lane >> 1;
            int lc = (lane & 1) * 8;
            int row = r0 + lr;
            if (row < M) {
#pragma unroll
                for (int c = 0; c < 8; c += 4) {
                    int col = c0 + lc + c;
                    float4 o;
                    o.x = fmaxf(Cw[lr * 16 + lc + c + 0] + bias[col + 0], 0.0f);
                    o.y = fmaxf(Cw[lr * 16 + lc + c + 1] + bias[col + 1], 0.0f);
                    o.z = fmaxf(Cw[lr * 16 + lc + c + 2] + bias[col + 2], 0.0f);
                    o.w = fmaxf(Cw[lr * 16 + lc + c + 3] + bias[col + 3], 0.0f);
                    *(float4*)(C + (size_t)row * OF + col) = o;
                }
            }
            __syncwarp();
        }
    }
}

// ---------------- launch ----------------
extern "C" void kernel_launch(void* const* d_in, const int* in_sizes, int n_in,
                              void* d_out, int out_size) {
    const float* signal = (const float*)d_in[0];
    const int*   src    = (const int*)d_in[1];
    const int*   dst    = (const int*)d_in[2];
    const float* lam    = (const float*)d_in[3];
    const float* W      = (const float*)d_in[4];
    const float* b      = (const float*)d_in[5];
    float* out = (float*)d_out;

    const int E = in_sizes[1];
    const int EB = (E + 255) / 256;

    // degrees + CSR (multi-block scan)
    zero_deg_kernel<<<(NN + 255) / 256, 256>>>();
    deg_kernel<<<EB, 256>>>(dst, E);
    scan1_kernel<<<SCAN_B, 1024>>>();
    scan2_kernel<<<1, 64>>>();
    scan3_kernel<<<SCAN_B, 1024>>>();
    fill_kernel<<<EB, 256>>>(src, dst, E);

    // X0
    init_kernel<<<(NN * 16 + 255) / 256, 256>>>(signal);

    // Chebyshev passes (warp per node, fused gather+combine)
    const int CB = (NN * 32 + 255) / 256;
    cheb_step_kernel<<<CB, 256>>>(lam, /*in*/0,   /*out*/64,  /*p1*/0,   /*p2*/0,  1);
    cheb_step_kernel<<<CB, 256>>>(lam, /*in*/64,  /*out*/128, /*p1*/64,  /*p2*/0,  2);
    cheb_step_kernel<<<CB, 256>>>(lam, /*in*/128, /*out*/192, /*p1*/128, /*p2*/64, 2);

    // out = relu(Xt @ W + b)  -- 2-stage pipelined tf32 tensor cores
    dim3 grid(OF / GBN, (NN + GBM - 1) / GBM);
    gemm_tf32<<<grid, 256>>>(W, b, out, NN);
}

// round 9
// speedup vs baseline: 1.4542x; 1.0219x over previous
#include <cuda_runtime.h>
#include <mma.h>
using namespace nvcuda;

#define NN 50000
#define F  64        // in feats
#define KK 256       // F * K(=4) = GEMM K dim
#define OF 256       // out feats
#define EE 800000
#define SCAN_B 49    // ceil(NN/1024)

// ---- scratch (static __device__ arrays; no allocation allowed) ----
// NOTE: g_deg relies on zero-init at module load; scan3 re-zeroes it after use,
// so every call (and every graph replay) starts from a zeroed array.
__device__ int   g_deg[NN];                 // in-degree (int)
__device__ int   g_part[SCAN_B];            // per-block partial sums
__device__ float g_dsq[NN];                 // rsqrt(max(deg,1))
__device__ int   g_rowptr[NN + 1];          // CSR row pointers (in-edges by dst)
__device__ int   g_fill[NN];                // fill counters
__device__ int   g_col[EE];                 // CSR column (src node of each in-edge)
__device__ float g_Xt[(size_t)NN * KK];     // packed [X0 | X1 | X2 | X3]

// ---------------- degree ----------------
__global__ void deg_kernel(const int* __restrict__ dst, int E) {
    int e = blockIdx.x * blockDim.x + threadIdx.x;
    if (e < E) atomicAdd(&g_deg[dst[e]], 1);
}

// ---- 3-phase scan: block sums -> scan partials -> block scan + outputs ----
__global__ __launch_bounds__(1024)
void scan1_kernel() {
    __shared__ int red[32];
    int i = blockIdx.x * 1024 + threadIdx.x;
    int d = (i < NN) ? g_deg[i] : 0;
    for (int o = 16; o > 0; o >>= 1) d += __shfl_down_sync(0xffffffff, d, o);
    if ((threadIdx.x & 31) == 0) red[threadIdx.x >> 5] = d;
    __syncthreads();
    if (threadIdx.x < 32) {
        int v = red[threadIdx.x];
        for (int o = 16; o > 0; o >>= 1) v += __shfl_down_sync(0xffffffff, v, o);
        if (threadIdx.x == 0) g_part[blockIdx.x] = v;
    }
}

__global__ void scan2_kernel() {   // 1 block, 64 threads: exclusive scan of 49 partials
    __shared__ int sh[64];
    int t = threadIdx.x;
    int v = (t < SCAN_B) ? g_part[t] : 0;
    sh[t] = v;
    __syncthreads();
    for (int off = 1; off < 64; off <<= 1) {
        int u = (t >= off) ? sh[t - off] : 0;
        __syncthreads();
        sh[t] += u;
        __syncthreads();
    }
    if (t < SCAN_B) g_part[t] = sh[t] - v;   // exclusive
    if (t == 0) g_rowptr[NN] = sh[63];
}

__global__ __launch_bounds__(1024)
void scan3_kernel() {
    __shared__ int sh[1024];
    int t = threadIdx.x;
    int i = blockIdx.x * 1024 + t;
    int d = (i < NN) ? g_deg[i] : 0;
    sh[t] = d;
    __syncthreads();
    for (int off = 1; off < 1024; off <<= 1) {
        int u = (t >= off) ? sh[t - off] : 0;
        __syncthreads();
        sh[t] += u;
        __syncthreads();
    }
    if (i < NN) {
        g_rowptr[i] = g_part[blockIdx.x] + sh[t] - d;   // exclusive prefix
        g_fill[i] = 0;
        g_dsq[i] = rsqrtf(fmaxf((float)d, 1.0f));
        g_deg[i] = 0;                                   // re-zero for next call
    }
}

__global__ void fill_kernel(const int* __restrict__ src,
                            const int* __restrict__ dst, int E) {
    int e = blockIdx.x * blockDim.x + threadIdx.x;
    if (e >= E) return;
    int d = dst[e];
    int pos = g_rowptr[d] + atomicAdd(&g_fill[d], 1);
    g_col[pos] = src[e];
}

// ---------------- init: X0 into Xt chunk0 ----------------
__global__ void init_kernel(const float* __restrict__ sig) {
    int i = blockIdx.x * blockDim.x + threadIdx.x;
    if (i >= NN * (F / 4)) return;
    int row = i >> 4;
    int c4  = i & 15;
    float4 v = ((const float4*)sig)[i];
    ((float4*)(g_Xt + (size_t)row * KK))[c4] = v;
}

// ---------------- fused Chebyshev step: gather + combine, no atomics ----------------
// warp per node, 4-edge unroll for MLP
__global__ __launch_bounds__(256)
void cheb_step_kernel(const float* __restrict__ lam,
                      int in_off, int out_off, int p1_off, int p2_off, int step) {
    int gtid = blockIdx.x * blockDim.x + threadIdx.x;
    int v = gtid >> 5;
    int lane = gtid & 31;
    if (v >= NN) return;

    int p   = g_rowptr[v];
    int end = g_rowptr[v + 1];
    float ax = 0.0f, ay = 0.0f;

    const float* Xin = g_Xt + in_off + lane * 2;
    for (; p + 3 < end; p += 4) {
        int s0 = g_col[p];
        int s1 = g_col[p + 1];
        int s2 = g_col[p + 2];
        int s3 = g_col[p + 3];
        float d0 = g_dsq[s0];
        float d1 = g_dsq[s1];
        float d2 = g_dsq[s2];
        float d3 = g_dsq[s3];
        float2 x0 = *(const float2*)(Xin + (size_t)s0 * KK);
        float2 x1 = *(const float2*)(Xin + (size_t)s1 * KK);
        float2 x2 = *(const float2*)(Xin + (size_t)s2 * KK);
        float2 x3 = *(const float2*)(Xin + (size_t)s3 * KK);
        ax += d0 * x0.x + d1 * x1.x + d2 * x2.x + d3 * x3.x;
        ay += d0 * x0.y + d1 * x1.y + d2 * x2.y + d3 * x3.y;
    }
    for (; p < end; p++) {
        int s0 = g_col[p];
        float d0 = g_dsq[s0];
        float2 x0 = *(const float2*)(Xin + (size_t)s0 * KK);
        ax += d0 * x0.x;
        ay += d0 * x0.y;
    }

    float dsv = g_dsq[v];
    float r = 2.0f / lam[0];
    float Lx = ax * dsv, Ly = ay * dsv;

    const float* base = g_Xt + (size_t)v * KK + lane * 2;
    float2 p1 = *(const float2*)(base + p1_off);
    float2 out;
    if (step == 1) {
        out.x = -r * Lx + (r - 1.0f) * p1.x;
        out.y = -r * Ly + (r - 1.0f) * p1.y;
    } else {
        float2 p2 = *(const float2*)(base + p2_off);
        out.x = -2.0f * r * Lx + 2.0f * (r - 1.0f) * p1.x - p2.x;
        out.y = -2.0f * r * Ly + 2.0f * (r - 1.0f) * p1.y - p2.y;
    }
    *(float2*)(g_Xt + (size_t)v * KK + out_off + lane * 2) = out;
}

// ---------------- 2-stage pipelined tf32 tensor-core GEMM + bias + ReLU ----------------
#define GBM 128
#define GBN 128
#define GBK 16
#define AROW 28
#define BROW 140
#define ASTG (GBM * AROW)          // 3584
#define STG  (ASTG + GBK * BROW)   // 5824 floats / stage

__device__ __forceinline__ void cp16(float* dstp, const float* src, int sz) {
    unsigned saddr = (unsigned)__cvta_generic_to_shared(dstp);
    asm volatile("cp.async.ca.shared.global [%0], [%1], 16, %2;"
                 :: "r"(saddr), "l"(src), "r"(sz));
}

__global__ __launch_bounds__(256)
void gemm_tf32(const float* __restrict__ W, const float* __restrict__ bias,
               float* __restrict__ C, int M) {
    __shared__ float sm[2 * STG];   // 46.6 KB

    int bx = blockIdx.x, by = blockIdx.y;
    int tid = threadIdx.x;
    int warp = tid >> 5, lane = tid & 31;
    int wm = warp >> 2;
    int wn = warp & 3;

    wmma::fragment<wmma::accumulator, 16, 16, 8, float> acc[4][2];
#pragma unroll
    for (int i = 0; i < 4; i++)
#pragma unroll
        for (int j = 0; j < 2; j++) wmma::fill_fragment(acc[i][j], 0.0f);

    const int NT = KK / GBK;   // 16

    auto load_stage = [&](int t, int stg) {
        float* s = sm + stg * STG;
        int k0 = t * GBK;
#pragma unroll
        for (int it = 0; it < 2; it++) {
            int idx = tid + it * 256;
            int row = idx >> 2, c4 = idx & 3;
            int gr = by * GBM + row;
            int grc = (gr < M) ? gr : (M - 1);
            const float* srcp = g_Xt + (size_t)grc * KK + k0 + c4 * 4;
            cp16(s + row * AROW + c4 * 4, srcp, (gr < M) ? 16 : 0);
        }
#pragma unroll
        for (int it = 0; it < 2; it++) {
            int idx = tid + it * 256;
            int row = idx >> 5, c4 = idx & 31;
            const float* srcp = W + (size_t)(k0 + row) * OF + bx * GBN + c4 * 4;
            cp16(s + ASTG + row * BROW + c4 * 4, srcp, 16);
        }
        asm volatile("cp.async.commit_group;");
    };

    load_stage(0, 0);

    for (int t = 0; t < NT; t++) {
        if (t + 1 < NT) {
            load_stage(t + 1, (t + 1) & 1);
            asm volatile("cp.async.wait_group 1;");
        } else {
            asm volatile("cp.async.wait_group 0;");
        }
        __syncthreads();

        const float* s = sm + (t & 1) * STG;
#pragma unroll
        for (int kk = 0; kk < GBK; kk += 8) {
            wmma::fragment<wmma::matrix_a, 16, 16, 8, wmma::precision::tf32, wmma::row_major> af[4];
            wmma::fragment<wmma::matrix_b, 16, 16, 8, wmma::precision::tf32, wmma::row_major> bf[2];
#pragma unroll
            for (int i = 0; i < 4; i++) {
                wmma::load_matrix_sync(af[i], s + (wm * 64 + i * 16) * AROW + kk, AROW);
#pragma unroll
                for (int e = 0; e < af[i].num_elements; e++)
                    af[i].x[e] = wmma::__float_to_tf32(af[i].x[e]);
            }
#pragma unroll
            for (int j = 0; j < 2; j++) {
                wmma::load_matrix_sync(bf[j], s + ASTG + kk * BROW + wn * 32 + j * 16, BROW);
#pragma unroll
                for (int e = 0; e < bf[j].num_elements; e++)
                    bf[j].x[e] = wmma::__float_to_tf32(bf[j].x[e]);
            }
#pragma unroll
            for (int i = 0; i < 4; i++)
#pragma unroll
                for (int j = 0; j < 2; j++)
                    wmma::mma_sync(acc[i][j], af[i], bf[j], acc[i][j]);
        }
        __syncthreads();
    }

    float* Cw = sm + warp * 256;
#pragma unroll
    for (int i = 0; i < 4; i++) {
#pragma unroll
        for (int j = 0; j < 2; j++) {
            wmma::store_matrix_sync(Cw, acc[i][j], 16, wmma::mem_row_major);
            __syncwarp();
            int r0 = by * GBM + wm * 64 + i * 16;
            int c0 = bx * GBN + wn * 32 + j * 16;
            int lr = lane >> 1;
            int lc = (lane & 1) * 8;
            int row = r0 + lr;
            if (row < M) {
#pragma unroll
                for (int c = 0; c < 8; c += 4) {
                    int col = c0 + lc + c;
                    float4 o;
                    o.x = fmaxf(Cw[lr * 16 + lc + c + 0] + bias[col + 0], 0.0f);
                    o.y = fmaxf(Cw[lr * 16 + lc + c + 1] + bias[col + 1], 0.0f);
                    o.z = fmaxf(Cw[lr * 16 + lc + c + 2] + bias[col + 2], 0.0f);
                    o.w = fmaxf(Cw[lr * 16 + lc + c + 3] + bias[col + 3], 0.0f);
                    *(float4*)(C + (size_t)row * OF + col) = o;
                }
            }
            __syncwarp();
        }
    }
}

// ---------------- launch ----------------
extern "C" void kernel_launch(void* const* d_in, const int* in_sizes, int n_in,
                              void* d_out, int out_size) {
    const float* signal = (const float*)d_in[0];
    const int*   src    = (const int*)d_in[1];
    const int*   dst    = (const int*)d_in[2];
    const float* lam    = (const float*)d_in[3];
    const float* W      = (const float*)d_in[4];
    const float* b      = (const float*)d_in[5];
    float* out = (float*)d_out;

    const int E = in_sizes[1];
    const int EB = (E + 255) / 256;

    // degrees + CSR (g_deg arrives zeroed: module-load init on call 1, scan3 re-zeroes after)
    deg_kernel<<<EB, 256>>>(dst, E);
    scan1_kernel<<<SCAN_B, 1024>>>();
    scan2_kernel<<<1, 64>>>();
    scan3_kernel<<<SCAN_B, 1024>>>();
    fill_kernel<<<EB, 256>>>(src, dst, E);

    // X0
    init_kernel<<<(NN * 16 + 255) / 256, 256>>>(signal);

    // Chebyshev passes (warp per node, fused gather+combine, 4-edge unroll)
    const int CB = (NN * 32 + 255) / 256;
    cheb_step_kernel<<<CB, 256>>>(lam, /*in*/0,   /*out*/64,  /*p1*/0,   /*p2*/0,  1);
    cheb_step_kernel<<<CB, 256>>>(lam, /*in*/64,  /*out*/128, /*p1*/64,  /*p2*/0,  2);
    cheb_step_kernel<<<CB, 256>>>(lam, /*in*/128, /*out*/192, /*p1*/128, /*p2*/64, 2);

    // out = relu(Xt @ W + b)  -- 2-stage pipelined tf32 tensor cores
    dim3 grid(OF / GBN, (NN + GBM - 1) / GBM);
    gemm_tf32<<<grid, 256>>>(W, b, out, NN);
}